// round 1
// baseline (speedup 1.0000x reference)
#include <cuda_runtime.h>

// Problem constants (from reference)
#define NWIN   16
#define NSTEP  16          // 1 + NG + NF
#define NP     256         // NWIN * NSTEP pairs
#define TT     400
#define DIMV   64
#define NG     5
#define NF     10
#define GAMMA_F 5.0f
#define INVG_F  0.2f
#define BIG_F   1e10f
#define TILE    80         // 400 = 5 * 80, zero edge waste

// Scratch: __device__ globals (no cudaMalloc allowed)
__device__ float g_D[(size_t)NP * TT * TT];   // 163.84 MB cost matrices
__device__ float g_norm[NP * TT];             // per-row squared norms
__device__ float g_dists[NP];                 // soft-DTW distances

// ---------------------------------------------------------------------------
// Phase 0: row squared norms. One warp per (pair,row); 2 loads + shuffle tree.
// ---------------------------------------------------------------------------
__global__ void norm_kernel(const float* __restrict__ data) {
    int w = blockIdx.x * (blockDim.x >> 5) + (threadIdx.x >> 5);
    int lane = threadIdx.x & 31;
    const float* row = data + (size_t)w * DIMV;
    float v0 = row[lane];
    float v1 = row[lane + 32];
    float s = v0 * v0 + v1 * v1;
    #pragma unroll
    for (int o = 16; o > 0; o >>= 1) s += __shfl_xor_sync(0xffffffffu, s, o);
    if (lane == 0) g_norm[w] = s;
}

// ---------------------------------------------------------------------------
// Phase 1: D[p][i][j] = na[i] + nb[j] - 2 * dot(A_i, B_j)
// 80x80 tile per CTA, 256 threads, 5x5 microtile, full K=64 in smem.
// Smem row stride 65: bank(b-load) = (5*tx + ...) mod 32, gcd(5,32)=1 -> no conflict.
// ---------------------------------------------------------------------------
__global__ __launch_bounds__(256) void d_kernel(const float* __restrict__ data) {
    int p  = blockIdx.z;
    int ti = blockIdx.y, tj = blockIdx.x;
    const float* A = data + (size_t)(p & ~(NSTEP - 1)) * TT * DIMV;  // window anchor
    const float* B = data + (size_t)p * TT * DIMV;

    __shared__ float As[TILE][DIMV + 1];
    __shared__ float Bs[TILE][DIMV + 1];

    int tid = threadIdx.x;
    // Load tiles: 80 rows x 64 cols = 1280 float4, 5 per thread, fully coalesced.
    #pragma unroll
    for (int it = tid; it < TILE * 16; it += 256) {
        int row = it >> 4, c4 = (it & 15) * 4;
        float4 va = *(const float4*)(A + (size_t)(ti * TILE + row) * DIMV + c4);
        float4 vb = *(const float4*)(B + (size_t)(tj * TILE + row) * DIMV + c4);
        As[row][c4 + 0] = va.x; As[row][c4 + 1] = va.y;
        As[row][c4 + 2] = va.z; As[row][c4 + 3] = va.w;
        Bs[row][c4 + 0] = vb.x; Bs[row][c4 + 1] = vb.y;
        Bs[row][c4 + 2] = vb.z; Bs[row][c4 + 3] = vb.w;
    }
    __syncthreads();

    int tx = tid & 15, ty = tid >> 4;
    float acc[5][5];
    #pragma unroll
    for (int r = 0; r < 5; r++)
        #pragma unroll
        for (int c = 0; c < 5; c++) acc[r][c] = 0.0f;

    #pragma unroll 4
    for (int k = 0; k < DIMV; k++) {
        float a[5], b[5];
        #pragma unroll
        for (int r = 0; r < 5; r++) a[r] = As[ty * 5 + r][k];
        #pragma unroll
        for (int c = 0; c < 5; c++) b[c] = Bs[tx * 5 + c][k];
        #pragma unroll
        for (int r = 0; r < 5; r++)
            #pragma unroll
            for (int c = 0; c < 5; c++) acc[r][c] += a[r] * b[c];
    }

    const float* nA = g_norm + (p & ~(NSTEP - 1)) * TT + ti * TILE + ty * 5;
    const float* nB = g_norm + p * TT + tj * TILE + tx * 5;
    float na[5], nb[5];
    #pragma unroll
    for (int r = 0; r < 5; r++) na[r] = nA[r];
    #pragma unroll
    for (int c = 0; c < 5; c++) nb[c] = nB[c];

    float* Dp = g_D + (size_t)p * TT * TT;
    #pragma unroll
    for (int r = 0; r < 5; r++) {
        int gi = ti * TILE + ty * 5 + r;
        #pragma unroll
        for (int c = 0; c < 5; c++) {
            int gj = tj * TILE + tx * 5 + c;
            Dp[(size_t)gi * TT + gj] = na[r] + nb[c] - 2.0f * acc[r][c];
        }
    }
}

// ---------------------------------------------------------------------------
// Phase 2: soft-DTW anti-diagonal DP. One CTA per pair, thread i owns DP row i.
// diag k element i == R[i, k-i]. Restricted to [1..la]x[1..lb] box (monotone
// recurrence: R[la,lb] never reads outside it), k up to la+lb only.
// ---------------------------------------------------------------------------
__global__ __launch_bounds__(416) void dp_kernel(const int* __restrict__ lens) {
    int p  = blockIdx.x;
    int la = lens[p & ~(NSTEP - 1)];
    int lb = lens[p];

    __shared__ float buf[3][416];
    int i = threadIdx.x;

    if (i <= TT) {
        buf[0][i] = (i == 0) ? 0.0f : BIG_F;  // diag 0: R[0,0]=0, rest BIG
        buf[1][i] = BIG_F;                     // diag 1: all BIG
    }
    __syncthreads();

    const float* drow = g_D + (size_t)p * TT * TT + (size_t)((i >= 1 ? i : 1) - 1) * TT;
    bool act  = (i >= 1 && i <= la);
    int  kmax = la + lb;

    float* p2  = buf[0];
    float* p1  = buf[1];
    float* cur = buf[2];

    for (int k = 2; k <= kmax; k++) {
        float r = BIG_F;
        int j = k - i;
        if (act && j >= 1 && j <= lb) {
            float a = p2[i - 1];   // R[i-1, j-1]
            float b = p1[i - 1];   // R[i-1, j]
            float c = p1[i];       // R[i,   j-1]
            float m = fminf(a, fminf(b, c));
            float s = __expf((m - a) * INVG_F)
                    + __expf((m - b) * INVG_F)
                    + __expf((m - c) * INVG_F);
            r = drow[j - 1] + m - GAMMA_F * __logf(s);
        }
        if (i <= TT) cur[i] = r;
        __syncthreads();
        float* t = p2; p2 = p1; p1 = cur; cur = t;
    }

    if (i == 0) g_dists[p] = p1[la] / (float)kmax;   // R[la,lb] / (la+lb)
}

// ---------------------------------------------------------------------------
// Phase 3: contrastive loss over 16 windows -> scalar mean.
// ---------------------------------------------------------------------------
__global__ void reduce_kernel(const float* __restrict__ margin,
                              float* __restrict__ out) {
    __shared__ float lv[NWIN];
    int tid = threadIdx.x;
    if (tid < NWIN) {
        const float* dw = g_dists + tid * NSTEP;
        float daa = dw[0];
        float mg  = margin[0];
        float ssum = 0.0f;
        int nz = 1;
        #pragma unroll
        for (int s = 1; s <= NG; s++) {
            float v = dw[s] - daa;
            ssum += v;
            nz += (v != 0.0f);
        }
        #pragma unroll
        for (int s = 1 + NG; s < 1 + NG + NF; s++) {
            float v = mg - (dw[s] - daa);
            v = fmaxf(v, 0.0f);
            ssum += v;
            nz += (v != 0.0f);
        }
        lv[tid] = ssum / (float)nz;
    }
    __syncthreads();
    if (tid == 0) {
        float t = 0.0f;
        #pragma unroll
        for (int w = 0; w < NWIN; w++) t += lv[w];
        out[0] = t * (1.0f / NWIN);
    }
}

// ---------------------------------------------------------------------------
extern "C" void kernel_launch(void* const* d_in, const int* in_sizes, int n_in,
                              void* d_out, int out_size) {
    const float* data   = (const float*)d_in[0];
    const float* margin = (const float*)d_in[1];
    const int*   lens   = (const int*)d_in[2];
    float*       out    = (float*)d_out;

    norm_kernel<<<(NP * TT) / 8, 256>>>(data);          // 8 warps/block, 1 row/warp
    d_kernel<<<dim3(5, 5, NP), 256>>>(data);            // 25 tiles x 256 pairs
    dp_kernel<<<NP, 416>>>(lens);                       // 1 CTA per pair
    reduce_kernel<<<1, 32>>>(margin, out);
}